// round 8
// baseline (speedup 1.0000x reference)
#include <cuda_runtime.h>
#include <cuda_bf16.h>
#include <cstdint>
#include <cstddef>

// Problem dims
#define B_  64
#define S_  512
#define T_  64
#define H_  512
#define D_  512
#define G_  1536   // 3*H

// ---------------- scratch (static device allocations) ----------------
__device__ float g_gi_pre [B_ * S_ * G_];
__device__ float g_gi_post[B_ * S_ * G_];
__device__ float g_gi_dec [B_ * T_ * G_];
__device__ float g_WT_pre [D_ * G_];
__device__ float g_WT_post[D_ * G_];
__device__ float g_WT_dec [D_ * G_];
__device__ float g_states_pre [S_ * B_ * H_];
__device__ float g_states_post[S_ * B_ * H_];
__device__ float g_dstates    [T_ * B_ * H_];
__device__ float g_dec_h0 [B_ * H_];
__device__ float g_score  [B_ * 2 * S_];
__device__ float g_hscore [B_ * T_];
__device__ int   g_dec_tokens[B_ * T_];
__device__ unsigned int g_bar_enc;
__device__ unsigned int g_bar_dec;

// ---------------- helpers ----------------
__device__ __forceinline__ float fast_sigmoid(float x) {
    return 1.0f / (1.0f + __expf(-x));
}

__device__ __forceinline__ float blockReduce128(float v) {
    __shared__ float red[4];
    #pragma unroll
    for (int o = 16; o; o >>= 1) v += __shfl_xor_sync(0xffffffffu, v, o);
    if ((threadIdx.x & 31) == 0) red[threadIdx.x >> 5] = v;
    __syncthreads();
    if (threadIdx.x == 0) v = red[0] + red[1] + red[2] + red[3];
    return v;
}

__device__ __forceinline__ float pk_lo(unsigned long long p) {
    return __uint_as_float((unsigned)(p & 0xffffffffull));
}
__device__ __forceinline__ float pk_hi(unsigned long long p) {
    return __uint_as_float((unsigned)(p >> 32));
}

// L2-only (bypass L1) vector load/store for cross-block h exchange
__device__ __forceinline__ float4 ldg_cg_v4(const float* p) {
    float4 v;
    asm volatile("ld.global.cg.v4.f32 {%0,%1,%2,%3},[%4];"
                 : "=f"(v.x), "=f"(v.y), "=f"(v.z), "=f"(v.w) : "l"(p));
    return v;
}
__device__ __forceinline__ void stg_cg_f32(float* p, float v) {
    asm volatile("st.global.cg.f32 [%0],%1;" :: "l"(p), "f"(v) : "memory");
}

// ---------------- 0. barrier reset ----------------
__global__ void reset_bar_kernel() {
    if (threadIdx.x == 0) { g_bar_enc = 0u; g_bar_dec = 0u; }
}

// ---------------- 1. transpose Wih (1536 x 512) -> WT (512 x 1536) ----------------
__global__ void transpose_k(const float* __restrict__ src, float* __restrict__ dst) {
    __shared__ float tile[32][33];
    int x = blockIdx.x * 32 + threadIdx.x;
    int y = blockIdx.y * 32 + threadIdx.y;
    #pragma unroll
    for (int i = 0; i < 32; i += 8)
        tile[threadIdx.y + i][threadIdx.x] = src[(size_t)(y + i) * D_ + x];
    __syncthreads();
    int x2 = blockIdx.y * 32 + threadIdx.x;
    int y2 = blockIdx.x * 32 + threadIdx.y;
    #pragma unroll
    for (int i = 0; i < 32; i += 8)
        dst[(size_t)(y2 + i) * G_ + x2] = tile[threadIdx.x][threadIdx.y + i];
}

// ---------------- 2. build decoder tokens ----------------
__global__ void dec_tokens_kernel(const int* __restrict__ pre_seq, const int* __restrict__ trg) {
    int idx = blockIdx.x * blockDim.x + threadIdx.x;
    if (idx >= B_ * T_) return;
    int b = idx >> 6;
    int t = idx & 63;
    g_dec_tokens[idx] = (t == 0) ? pre_seq[b * S_ + (S_ - 1)] : trg[b * T_ + t - 1];
}

// ---------------- 3. gi GEMM (128x128x8 tiles, 256 thr, 8x8/thread) ----------------
__global__ void gi_gemm(const int* __restrict__ tokens,
                        const float* __restrict__ emb,
                        const float* __restrict__ WT,
                        const float* __restrict__ bias,
                        float* __restrict__ out) {
    __shared__ float As[8][128];
    __shared__ float Bs[8][128];
    int tid  = threadIdx.x;
    int row0 = blockIdx.y * 128;
    int col0 = blockIdx.x * 128;

    int ar = tid >> 1;
    int ac = (tid & 1) * 4;
    int token = tokens[row0 + ar];
    const float* arow = emb + (size_t)token * D_ + ac;

    int br = tid >> 5;
    int bc = (tid & 31) * 4;
    const float* bptr = WT + (size_t)br * G_ + col0 + bc;

    int tr = (tid >> 4) * 8;
    int tc = (tid & 15) * 8;

    float acc[8][8];
    #pragma unroll
    for (int i = 0; i < 8; i++)
        #pragma unroll
        for (int j = 0; j < 8; j++) acc[i][j] = 0.0f;

    for (int k0 = 0; k0 < D_; k0 += 8) {
        float4 av = *(const float4*)(arow + k0);
        As[ac + 0][ar] = av.x; As[ac + 1][ar] = av.y;
        As[ac + 2][ar] = av.z; As[ac + 3][ar] = av.w;
        float4 bv = *(const float4*)(bptr + (size_t)k0 * G_);
        *(float4*)&Bs[br][bc] = bv;
        __syncthreads();
        #pragma unroll
        for (int k = 0; k < 8; k++) {
            float a[8], bb[8];
            *(float4*)(a)      = *(const float4*)&As[k][tr];
            *(float4*)(a + 4)  = *(const float4*)&As[k][tr + 4];
            *(float4*)(bb)     = *(const float4*)&Bs[k][tc];
            *(float4*)(bb + 4) = *(const float4*)&Bs[k][tc + 4];
            #pragma unroll
            for (int i = 0; i < 8; i++)
                #pragma unroll
                for (int j = 0; j < 8; j++)
                    acc[i][j] = fmaf(a[i], bb[j], acc[i][j]);
        }
        __syncthreads();
    }

    #pragma unroll
    for (int i = 0; i < 8; i++) {
        #pragma unroll
        for (int j = 0; j < 8; j += 4) {
            float4 v;
            v.x = acc[i][j + 0] + bias[col0 + tc + j + 0];
            v.y = acc[i][j + 1] + bias[col0 + tc + j + 1];
            v.z = acc[i][j + 2] + bias[col0 + tc + j + 2];
            v.w = acc[i][j + 3] + bias[col0 + tc + j + 3];
            *(float4*)&out[(size_t)(row0 + tr + i) * G_ + col0 + tc + j] = v;
        }
    }
}

// ---------------- 4. persistent GRU recurrence ----------------
// Grid: 64 blocks per GRU (4 batch-quarters x 16 j-chunks of 32), 384 threads.
// Block tile: 16 batches x 96 n-rows (32 j x 3 gates), full K=512 per step.
// smem: W (16B (kq,n) groups) 192KB persistent + h stage 32KB (gh overlays h).
#define PERS_THREADS 384
#define PERS_SMEM ((96 * 512 + 16 * 512) * 4)   // 229,376 B

__global__ __launch_bounds__(PERS_THREADS, 1)
void gru_persistent(const float* __restrict__ Whh0, const float* __restrict__ bhh0,
                    const float* __restrict__ gi0,  float* __restrict__ st0,
                    const float* __restrict__ Whh1, const float* __restrict__ bhh1,
                    const float* __restrict__ gi1,  float* __restrict__ st1,
                    const float* __restrict__ hinit,   // nullptr => zeros
                    int nsteps, int gi_sstride, int nblk, unsigned int* bar) {
    extern __shared__ float sm[];
    float* ws = sm;                 // 96*512 floats, (kq,n) 16B groups
    float* hs = sm + 96 * 512;      // 16*512 floats; gh overlays first 1536

    int tid  = threadIdx.x;
    int lane = tid & 31;
    int w    = tid >> 5;
    int g    = w >> 2;              // 0..2
    int bh   = w & 3;               // 0..3

    int bid  = blockIdx.x;
    int gru  = bid >> 6;
    int r    = bid & 63;
    int b0   = (r >> 4) * 16;
    int j0   = (r & 15) * 32;

    const float* Whh = gru ? Whh1 : Whh0;
    const float* bhh = gru ? bhh1 : bhh0;
    const float* gi  = gru ? gi1  : gi0;
    float*       st  = gru ? st1  : st0;

    // ---- load W tile once: rows n=(g,jl) -> grow = g*512 + j0 + jl ----
    for (int idx = tid; idx < 96 * 128; idx += PERS_THREADS) {
        int n  = idx >> 7;
        int kq = idx & 127;
        int gg = n >> 5, jl = n & 31;
        float4 v = *(const float4*)(Whh + ((size_t)(gg * H_ + j0 + jl)) * H_ + kq * 4);
        *(float4*)&ws[(kq * 96 + n) * 4] = v;
    }

    // per-thread constants
    uint32_t smem_base = (uint32_t)__cvta_generic_to_shared(sm);
    uint32_t ws_base   = smem_base;
    uint32_t hs_base   = smem_base + 96u * 512u * 4u;
    int n_self = g * 32 + lane;
    uint32_t wa0 = ws_base + (uint32_t)n_self * 16u;
    uint32_t hb0 = hs_base + (uint32_t)(bh * 4) * 2048u;

    // gate-phase constants: outputs idx in [0,512): b=idx>>5, jl=idx&31
    int o0 = tid;            // always < 512
    int o1 = tid + 384;      // valid if < 512
    int ob0 = o0 >> 5, ojl0 = o0 & 31;
    int ob1 = o1 >> 5, ojl1 = o1 & 31;
    float br0 = bhh[j0 + ojl0], bz0 = bhh[H_ + j0 + ojl0], bn0 = bhh[2 * H_ + j0 + ojl0];
    float br1 = 0.f, bz1 = 0.f, bn1 = 0.f;
    if (o1 < 512) { br1 = bhh[j0 + ojl1]; bz1 = bhh[H_ + j0 + ojl1]; bn1 = bhh[2 * H_ + j0 + ojl1]; }

    __syncthreads();

    for (int t = 0; t < nsteps; t++) {
        // ---- stage h_prev (16 rows) via L2 (.cg) ----
        const float* hp = (t == 0) ? hinit : (st + (size_t)(t - 1) * B_ * H_);
        if (hp) {
            const float* src = hp + (size_t)b0 * H_;
            for (int i = tid; i < 2048; i += PERS_THREADS) {
                float4 v = ldg_cg_v4(src + i * 4);
                *(float4*)&hs[i * 4] = v;
            }
        } else {
            float4 z = make_float4(0.f, 0.f, 0.f, 0.f);
            float4* dst = (float4*)hs;
            for (int i = tid; i < 2048; i += PERS_THREADS) dst[i] = z;
        }
        __syncthreads();

        // ---- K loop: acc[b] = sum_k W[n][k] * h[b][k] ----
        unsigned long long accA[4] = {0ull, 0ull, 0ull, 0ull};
        unsigned long long accB[4] = {0ull, 0ull, 0ull, 0ull};
        uint32_t wa = wa0;
        uint32_t hb = hb0;
        #pragma unroll 4
        for (int kq = 0; kq < 128; kq++) {
            unsigned long long w01, w23;
            asm("ld.shared.v2.u64 {%0,%1},[%2];" : "=l"(w01), "=l"(w23) : "r"(wa));
            wa += 96u * 16u;
            #pragma unroll
            for (int b = 0; b < 4; b++) {
                unsigned long long h01, h23;
                asm("ld.shared.v2.u64 {%0,%1},[%2];" : "=l"(h01), "=l"(h23)
                    : "r"(hb + (uint32_t)b * 2048u));
                asm("fma.rn.f32x2 %0,%1,%2,%0;" : "+l"(accA[b]) : "l"(w01), "l"(h01));
                asm("fma.rn.f32x2 %0,%1,%2,%0;" : "+l"(accB[b]) : "l"(w23), "l"(h23));
            }
            hb += 16u;
        }

        // ---- preload hprev for gate phase (before gh overlays hs) ----
        float hpv0 = hs[ob0 * H_ + j0 + ojl0];
        float hpv1 = (o1 < 512) ? hs[ob1 * H_ + j0 + ojl1] : 0.f;
        __syncthreads();

        // ---- write gh into overlay: gh[(g*16 + b)*32 + jl] ----
        #pragma unroll
        for (int b = 0; b < 4; b++) {
            float s = pk_lo(accA[b]) + pk_hi(accA[b]) + pk_lo(accB[b]) + pk_hi(accB[b]);
            hs[(g * 16 + bh * 4 + b) * 32 + lane] = s;
        }
        __syncthreads();

        // ---- gate phase (h_out stores via .cg -> L2) ----
        float* h_out = st + (size_t)t * B_ * H_;
        {
            int b = ob0, jl = ojl0, jg = j0 + jl, bg = b0 + b;
            const float* gp = gi + ((size_t)bg * gi_sstride + t) * G_;
            float hr = hs[(0 * 16 + b) * 32 + jl] + br0;
            float hz = hs[(1 * 16 + b) * 32 + jl] + bz0;
            float hn = hs[(2 * 16 + b) * 32 + jl] + bn0;
            float rr = fast_sigmoid(gp[jg] + hr);
            float zz = fast_sigmoid(gp[H_ + jg] + hz);
            float nn = tanhf(gp[2 * H_ + jg] + rr * hn);
            stg_cg_f32(h_out + (size_t)bg * H_ + jg, (1.0f - zz) * nn + zz * hpv0);
        }
        if (o1 < 512) {
            int b = ob1, jl = ojl1, jg = j0 + jl, bg = b0 + b;
            const float* gp = gi + ((size_t)bg * gi_sstride + t) * G_;
            float hr = hs[(0 * 16 + b) * 32 + jl] + br1;
            float hz = hs[(1 * 16 + b) * 32 + jl] + bz1;
            float hn = hs[(2 * 16 + b) * 32 + jl] + bn1;
            float rr = fast_sigmoid(gp[jg] + hr);
            float zz = fast_sigmoid(gp[H_ + jg] + hz);
            float nn = tanhf(gp[2 * H_ + jg] + rr * hn);
            stg_cg_f32(h_out + (size_t)bg * H_ + jg, (1.0f - zz) * nn + zz * hpv1);
        }

        // ---- grid barrier: release arrive, acquire wait ----
        __threadfence();
        __syncthreads();
        if (tid == 0) {
            asm volatile("red.release.gpu.global.add.u32 [%0],1;" :: "l"(bar) : "memory");
            unsigned int target = (unsigned int)(t + 1) * (unsigned int)nblk;
            unsigned int v;
            do {
                asm volatile("ld.acquire.gpu.global.u32 %0,[%1];" : "=r"(v) : "l"(bar) : "memory");
            } while (v < target);
        }
        __threadfence();
        __syncthreads();
    }
}

// ---------------- 5. enc_hidden -> decoder h0 ----------------
__global__ void enc_hidden_kernel(const float* __restrict__ enc_fc_w,
                                  const float* __restrict__ enc_fc_b) {
    int j = blockIdx.x, b = blockIdx.y;
    const float* hp = g_states_pre  + ((size_t)(S_ - 1) * B_ + b) * H_;
    const float* hq = g_states_post + ((size_t)(S_ - 1) * B_ + b) * H_;
    const float* wrow = enc_fc_w + (size_t)j * (2 * H_);
    float acc = 0.f;
    for (int k = threadIdx.x; k < H_; k += 128)
        acc += hp[k] * wrow[k] + hq[k] * wrow[H_ + k];
    acc = blockReduce128(acc);
    if (threadIdx.x == 0) g_dec_h0[b * H_ + j] = tanhf(acc + enc_fc_b[j]);
}

// ---------------- 6. score_enc ----------------
__global__ void score_enc_kernel(const float* __restrict__ out_w) {
    int c = blockIdx.x, b = blockIdx.y;
    int e = c >> 9, t = c & (S_ - 1);
    const float* src = (e ? g_states_post : g_states_pre) + ((size_t)t * B_ + b) * H_;
    float acc = 0.f;
    for (int h = threadIdx.x; h < H_; h += 128)
        acc += fmaxf(src[h], 0.f) * out_w[h];
    acc = blockReduce128(acc);
    if (threadIdx.x == 0) g_score[b * (2 * S_) + c] = acc;
}

// ---------------- 7. hscore ----------------
__global__ void hscore_kernel(const float* __restrict__ out_w, const float* __restrict__ out_b) {
    int t = blockIdx.x, b = blockIdx.y;
    const float* src = g_dstates + ((size_t)t * B_ + b) * H_;
    float acc = 0.f;
    for (int h = threadIdx.x; h < H_; h += 128)
        acc += fmaxf(src[h], 0.f) * out_w[H_ + h];
    acc = blockReduce128(acc);
    if (threadIdx.x == 0) g_hscore[b * T_ + t] = acc + out_b[0];
}

// ---------------- 8. final output: sigmoid fill ----------------
__global__ void output_kernel(float* __restrict__ out) {
    int idx = blockIdx.x * blockDim.x + threadIdx.x;
    int p  = idx >> 21;
    int r  = idx & ((1 << 21) - 1);
    int b  = r >> 15;
    int r2 = r & 32767;
    int t  = r2 >> 9;
    int s  = r2 & 511;
    float logit = g_score[b * (2 * S_) + p * S_ + s] + g_hscore[b * T_ + t];
    out[idx] = fast_sigmoid(logit);
}

// ---------------- host ----------------
extern "C" void kernel_launch(void* const* d_in, const int* in_sizes, int n_in,
                              void* d_out, int out_size) {
    const int*   pre_seq   = (const int*)  d_in[0];
    const int*   post_seq  = (const int*)  d_in[1];
    const int*   trg       = (const int*)  d_in[2];
    const float* emb       = (const float*)d_in[3];
    const float* pre_Wih   = (const float*)d_in[4];
    const float* pre_Whh   = (const float*)d_in[5];
    const float* pre_bih   = (const float*)d_in[6];
    const float* pre_bhh   = (const float*)d_in[7];
    const float* post_Wih  = (const float*)d_in[8];
    const float* post_Whh  = (const float*)d_in[9];
    const float* post_bih  = (const float*)d_in[10];
    const float* post_bhh  = (const float*)d_in[11];
    const float* enc_fc_w  = (const float*)d_in[12];
    const float* enc_fc_b  = (const float*)d_in[13];
    const float* dec_Wih   = (const float*)d_in[14];
    const float* dec_Whh   = (const float*)d_in[15];
    const float* dec_bih   = (const float*)d_in[16];
    const float* dec_bhh   = (const float*)d_in[17];
    const float* out_w     = (const float*)d_in[18];
    const float* out_b     = (const float*)d_in[19];
    float* out = (float*)d_out;

    float *gi_pre, *gi_post, *gi_dec, *wt_pre, *wt_post, *wt_dec;
    float *st_pre, *st_post, *dst, *dec_h0;
    int* dec_tok;
    unsigned int *bar_enc, *bar_dec;
    cudaGetSymbolAddress((void**)&gi_pre,  g_gi_pre);
    cudaGetSymbolAddress((void**)&gi_post, g_gi_post);
    cudaGetSymbolAddress((void**)&gi_dec,  g_gi_dec);
    cudaGetSymbolAddress((void**)&wt_pre,  g_WT_pre);
    cudaGetSymbolAddress((void**)&wt_post, g_WT_post);
    cudaGetSymbolAddress((void**)&wt_dec,  g_WT_dec);
    cudaGetSymbolAddress((void**)&st_pre,  g_states_pre);
    cudaGetSymbolAddress((void**)&st_post, g_states_post);
    cudaGetSymbolAddress((void**)&dst,     g_dstates);
    cudaGetSymbolAddress((void**)&dec_h0,  g_dec_h0);
    cudaGetSymbolAddress((void**)&dec_tok, g_dec_tokens);
    cudaGetSymbolAddress((void**)&bar_enc, g_bar_enc);
    cudaGetSymbolAddress((void**)&bar_dec, g_bar_dec);

    cudaFuncSetAttribute(gru_persistent, cudaFuncAttributeMaxDynamicSharedMemorySize, PERS_SMEM);

    reset_bar_kernel<<<1, 32>>>();

    dim3 tb(32, 8);
    transpose_k<<<dim3(16, 48), tb>>>(pre_Wih,  wt_pre);
    transpose_k<<<dim3(16, 48), tb>>>(post_Wih, wt_post);
    transpose_k<<<dim3(16, 48), tb>>>(dec_Wih,  wt_dec);

    dec_tokens_kernel<<<16, 256>>>(pre_seq, trg);

    gi_gemm<<<dim3(12, 256), 256>>>(pre_seq,  emb, wt_pre,  pre_bih,  gi_pre);
    gi_gemm<<<dim3(12, 256), 256>>>(post_seq, emb, wt_post, post_bih, gi_post);
    gi_gemm<<<dim3(12, 32),  256>>>(dec_tok,  emb, wt_dec,  dec_bih,  gi_dec);

    // encoder recurrence: one persistent kernel, both GRUs (128 blocks)
    gru_persistent<<<128, PERS_THREADS, PERS_SMEM>>>(
        pre_Whh, pre_bhh, gi_pre, st_pre,
        post_Whh, post_bhh, gi_post, st_post,
        nullptr, S_, S_, 128, bar_enc);

    enc_hidden_kernel<<<dim3(H_, B_), 128>>>(enc_fc_w, enc_fc_b);
    score_enc_kernel<<<dim3(2 * S_, B_), 128>>>(out_w);

    // decoder recurrence: one persistent kernel (64 blocks, gru index always 0)
    gru_persistent<<<64, PERS_THREADS, PERS_SMEM>>>(
        dec_Whh, dec_bhh, gi_dec, dst,
        dec_Whh, dec_bhh, gi_dec, dst,
        dec_h0, T_, T_, 64, bar_dec);

    hscore_kernel<<<dim3(T_, B_), 128>>>(out_w, out_b);
    output_kernel<<<(2 * B_ * T_ * S_) / 256, 256>>>(out);
}

// round 9
// speedup vs baseline: 1.1137x; 1.1137x over previous
#include <cuda_runtime.h>
#include <cuda_bf16.h>
#include <cstdint>
#include <cstddef>

// Problem dims
#define B_  64
#define S_  512
#define T_  64
#define H_  512
#define D_  512
#define G_  1536   // 3*H

// ---------------- scratch (static device allocations) ----------------
__device__ float g_gi_pre [B_ * S_ * G_];
__device__ float g_gi_post[B_ * S_ * G_];
__device__ float g_gi_dec [B_ * T_ * G_];
__device__ float g_WT_pre [D_ * G_];
__device__ float g_WT_post[D_ * G_];
__device__ float g_WT_dec [D_ * G_];
__device__ float g_states_pre [S_ * B_ * H_];
__device__ float g_states_post[S_ * B_ * H_];
__device__ float g_dstates    [T_ * B_ * H_];
__device__ float g_dec_h0 [B_ * H_];
__device__ float g_score  [B_ * 2 * S_];
__device__ float g_hscore [B_ * T_];
__device__ int   g_dec_tokens[B_ * T_];
__device__ unsigned int g_bar_enc;
__device__ unsigned int g_bar_dec;

// ---------------- helpers ----------------
__device__ __forceinline__ float fast_sigmoid(float x) {
    return 1.0f / (1.0f + __expf(-x));
}

__device__ __forceinline__ float blockReduce128(float v) {
    __shared__ float red[4];
    #pragma unroll
    for (int o = 16; o; o >>= 1) v += __shfl_xor_sync(0xffffffffu, v, o);
    if ((threadIdx.x & 31) == 0) red[threadIdx.x >> 5] = v;
    __syncthreads();
    if (threadIdx.x == 0) v = red[0] + red[1] + red[2] + red[3];
    return v;
}

__device__ __forceinline__ float pk_lo(unsigned long long p) {
    return __uint_as_float((unsigned)(p & 0xffffffffull));
}
__device__ __forceinline__ float pk_hi(unsigned long long p) {
    return __uint_as_float((unsigned)(p >> 32));
}

// L2-only (bypass L1) vector load/store for cross-block h exchange
__device__ __forceinline__ float4 ldg_cg_v4(const float* p) {
    float4 v;
    asm volatile("ld.global.cg.v4.f32 {%0,%1,%2,%3},[%4];"
                 : "=f"(v.x), "=f"(v.y), "=f"(v.z), "=f"(v.w) : "l"(p));
    return v;
}
__device__ __forceinline__ void stg_cg_f32(float* p, float v) {
    asm volatile("st.global.cg.f32 [%0],%1;" :: "l"(p), "f"(v) : "memory");
}

// ---------------- 0. barrier reset ----------------
__global__ void reset_bar_kernel() {
    if (threadIdx.x == 0) { g_bar_enc = 0u; g_bar_dec = 0u; }
}

// ---------------- 1. transpose Wih (1536 x 512) -> WT (512 x 1536) ----------------
__global__ void transpose_k(const float* __restrict__ src, float* __restrict__ dst) {
    __shared__ float tile[32][33];
    int x = blockIdx.x * 32 + threadIdx.x;
    int y = blockIdx.y * 32 + threadIdx.y;
    #pragma unroll
    for (int i = 0; i < 32; i += 8)
        tile[threadIdx.y + i][threadIdx.x] = src[(size_t)(y + i) * D_ + x];
    __syncthreads();
    int x2 = blockIdx.y * 32 + threadIdx.x;
    int y2 = blockIdx.x * 32 + threadIdx.y;
    #pragma unroll
    for (int i = 0; i < 32; i += 8)
        dst[(size_t)(y2 + i) * G_ + x2] = tile[threadIdx.x][threadIdx.y + i];
}

// ---------------- 2. build decoder tokens ----------------
__global__ void dec_tokens_kernel(const int* __restrict__ pre_seq, const int* __restrict__ trg) {
    int idx = blockIdx.x * blockDim.x + threadIdx.x;
    if (idx >= B_ * T_) return;
    int b = idx >> 6;
    int t = idx & 63;
    g_dec_tokens[idx] = (t == 0) ? pre_seq[b * S_ + (S_ - 1)] : trg[b * T_ + t - 1];
}

// ---------------- 3. gi GEMM (128x128x8 tiles, 256 thr, 8x8/thread) ----------------
__global__ void gi_gemm(const int* __restrict__ tokens,
                        const float* __restrict__ emb,
                        const float* __restrict__ WT,
                        const float* __restrict__ bias,
                        float* __restrict__ out) {
    __shared__ float As[8][128];
    __shared__ float Bs[8][128];
    int tid  = threadIdx.x;
    int row0 = blockIdx.y * 128;
    int col0 = blockIdx.x * 128;

    int ar = tid >> 1;
    int ac = (tid & 1) * 4;
    int token = tokens[row0 + ar];
    const float* arow = emb + (size_t)token * D_ + ac;

    int br = tid >> 5;
    int bc = (tid & 31) * 4;
    const float* bptr = WT + (size_t)br * G_ + col0 + bc;

    int tr = (tid >> 4) * 8;
    int tc = (tid & 15) * 8;

    float acc[8][8];
    #pragma unroll
    for (int i = 0; i < 8; i++)
        #pragma unroll
        for (int j = 0; j < 8; j++) acc[i][j] = 0.0f;

    for (int k0 = 0; k0 < D_; k0 += 8) {
        float4 av = *(const float4*)(arow + k0);
        As[ac + 0][ar] = av.x; As[ac + 1][ar] = av.y;
        As[ac + 2][ar] = av.z; As[ac + 3][ar] = av.w;
        float4 bv = *(const float4*)(bptr + (size_t)k0 * G_);
        *(float4*)&Bs[br][bc] = bv;
        __syncthreads();
        #pragma unroll
        for (int k = 0; k < 8; k++) {
            float a[8], bb[8];
            *(float4*)(a)      = *(const float4*)&As[k][tr];
            *(float4*)(a + 4)  = *(const float4*)&As[k][tr + 4];
            *(float4*)(bb)     = *(const float4*)&Bs[k][tc];
            *(float4*)(bb + 4) = *(const float4*)&Bs[k][tc + 4];
            #pragma unroll
            for (int i = 0; i < 8; i++)
                #pragma unroll
                for (int j = 0; j < 8; j++)
                    acc[i][j] = fmaf(a[i], bb[j], acc[i][j]);
        }
        __syncthreads();
    }

    #pragma unroll
    for (int i = 0; i < 8; i++) {
        #pragma unroll
        for (int j = 0; j < 8; j += 4) {
            float4 v;
            v.x = acc[i][j + 0] + bias[col0 + tc + j + 0];
            v.y = acc[i][j + 1] + bias[col0 + tc + j + 1];
            v.z = acc[i][j + 2] + bias[col0 + tc + j + 2];
            v.w = acc[i][j + 3] + bias[col0 + tc + j + 3];
            *(float4*)&out[(size_t)(row0 + tr + i) * G_ + col0 + tc + j] = v;
        }
    }
}

// ---------------- 4. persistent GRU recurrence (register-resident W) ----------------
// Grid: 64 blocks per GRU (4 batch-quarters x 16 j-chunks of 32), 384 threads.
// Warp w: g = w>>2 (gate), q = w&3 (k-quarter); lane = jl (hidden col within chunk).
// Each thread holds W[g*H + j0+jl][q*128 .. q*128+127] in 64 f32x2 registers for
// the whole kernel. Per step: h staged to smem (broadcast reads), k-partials
// exchanged via smem part[q][g][b][jl], then gate phase.
// smem: h 16*512 floats (32KB) + part 4*3*16*32 floats (24KB) = 56KB.
#define PERS_THREADS 384
#define PERS_SMEM ((16 * 512 + 4 * 3 * 16 * 32) * 4)   // 57,344 B

__global__ __launch_bounds__(PERS_THREADS, 1)
void gru_persistent(const float* __restrict__ Whh0, const float* __restrict__ bhh0,
                    const float* __restrict__ gi0,  float* __restrict__ st0,
                    const float* __restrict__ Whh1, const float* __restrict__ bhh1,
                    const float* __restrict__ gi1,  float* __restrict__ st1,
                    const float* __restrict__ hinit,   // nullptr => zeros
                    int nsteps, int gi_sstride, int nblk, unsigned int* bar) {
    extern __shared__ float sm[];
    float* hs   = sm;                  // [16][512]
    float* part = sm + 16 * 512;       // [4 q][3 g][16 b][32 jl]

    int tid  = threadIdx.x;
    int lane = tid & 31;               // jl
    int w    = tid >> 5;
    int q    = w & 3;                  // k-quarter
    int g    = w >> 2;                 // gate 0..2

    int bid  = blockIdx.x;
    int gru  = bid >> 6;
    int r    = bid & 63;
    int b0   = (r >> 4) * 16;
    int j0   = (r & 15) * 32;

    const float* Whh = gru ? Whh1 : Whh0;
    const float* bhh = gru ? bhh1 : bhh0;
    const float* gi  = gru ? gi1  : gi0;
    float*       st  = gru ? st1  : st0;

    // ---- load W slice into registers once: 128 floats = 64 f32x2 ----
    unsigned long long wreg[64];
    {
        const unsigned long long* wp = (const unsigned long long*)
            (Whh + ((size_t)(g * H_ + j0 + lane)) * H_ + q * 128);
        #pragma unroll
        for (int i = 0; i < 64; i++) wreg[i] = wp[i];
    }

    uint32_t smem_base = (uint32_t)__cvta_generic_to_shared(sm);
    uint32_t hq_base   = smem_base + (uint32_t)(q * 128) * 4u;   // + b*512*4 per b
    uint32_t part_base = smem_base + 16u * 512u * 4u;
    // this thread's partial slot stride: part[((q*3+g)*16 + b)*32 + lane]
    uint32_t part_my   = part_base + (uint32_t)(((q * 3 + g) * 16) * 32 + lane) * 4u;

    // gate-phase output assignments
    int o0 = tid;            // < 512 always (384)
    int o1 = tid + 384;      // valid if < 512 (tid < 128)
    int ob0 = o0 >> 5, ojl0 = o0 & 31;
    int ob1 = o1 >> 5, ojl1 = o1 & 31;

    for (int t = 0; t < nsteps; t++) {
        // ---- stage h_prev (16 rows x 512) via L2 (.cg) ----
        const float* hp = (t == 0) ? hinit : (st + (size_t)(t - 1) * B_ * H_);
        if (hp) {
            const float* src = hp + (size_t)b0 * H_;
            for (int i = tid; i < 2048; i += PERS_THREADS) {
                float4 v = ldg_cg_v4(src + i * 4);
                *(float4*)&hs[i * 4] = v;
            }
        } else {
            float4 z = make_float4(0.f, 0.f, 0.f, 0.f);
            float4* dst = (float4*)hs;
            for (int i = tid; i < 2048; i += PERS_THREADS) dst[i] = z;
        }
        __syncthreads();

        // ---- K loop: partial[b] = sum_{k in quarter} W[n][k] * h[b][k] ----
        for (int b = 0; b < 16; b++) {
            uint32_t ha = hq_base + (uint32_t)b * (512u * 4u);
            unsigned long long a0 = 0ull, a1 = 0ull;
            #pragma unroll
            for (int i = 0; i < 32; i++) {
                unsigned long long h0, h1;
                asm("ld.shared.v2.u64 {%0,%1},[%2];"
                    : "=l"(h0), "=l"(h1) : "r"(ha + (uint32_t)(i * 16)));
                asm("fma.rn.f32x2 %0,%1,%2,%0;" : "+l"(a0) : "l"(wreg[2 * i]),     "l"(h0));
                asm("fma.rn.f32x2 %0,%1,%2,%0;" : "+l"(a1) : "l"(wreg[2 * i + 1]), "l"(h1));
            }
            float s = pk_lo(a0) + pk_hi(a0) + pk_lo(a1) + pk_hi(a1);
            // part[((q*3+g)*16 + b)*32 + lane]
            asm volatile("st.shared.f32 [%0],%1;"
                         :: "r"(part_my + (uint32_t)b * (32u * 4u)), "f"(s));
        }
        __syncthreads();

        // ---- gate phase: 512 outputs (16 b x 32 jl) ----
        float* h_out = st + (size_t)t * B_ * H_;
        #pragma unroll
        for (int pass = 0; pass < 2; pass++) {
            int o = pass ? o1 : o0;
            if (pass && o >= 512) break;
            int b  = pass ? ob1 : ob0;
            int jl = pass ? ojl1 : ojl0;
            int jg = j0 + jl;
            int bg = b0 + b;
            // sum 4 q-partials per gate
            float hr = 0.f, hz = 0.f, hn = 0.f;
            #pragma unroll
            for (int qq = 0; qq < 4; qq++) {
                hr += part[((qq * 3 + 0) * 16 + b) * 32 + jl];
                hz += part[((qq * 3 + 1) * 16 + b) * 32 + jl];
                hn += part[((qq * 3 + 2) * 16 + b) * 32 + jl];
            }
            hr += __ldg(bhh + jg);
            hz += __ldg(bhh + H_ + jg);
            hn += __ldg(bhh + 2 * H_ + jg);
            const float* gp = gi + ((size_t)bg * gi_sstride + t) * G_;
            float rr = fast_sigmoid(gp[jg] + hr);
            float zz = fast_sigmoid(gp[H_ + jg] + hz);
            float nn = tanhf(gp[2 * H_ + jg] + rr * hn);
            float hprev = hs[b * H_ + jg];
            stg_cg_f32(h_out + (size_t)bg * H_ + jg, (1.0f - zz) * nn + zz * hprev);
        }

        // ---- grid barrier: release arrive, acquire wait ----
        __threadfence();
        __syncthreads();
        if (tid == 0) {
            asm volatile("red.release.gpu.global.add.u32 [%0],1;" :: "l"(bar) : "memory");
            unsigned int target = (unsigned int)(t + 1) * (unsigned int)nblk;
            unsigned int v;
            do {
                asm volatile("ld.acquire.gpu.global.u32 %0,[%1];" : "=r"(v) : "l"(bar) : "memory");
            } while (v < target);
        }
        __threadfence();
        __syncthreads();
    }
}

// ---------------- 5. enc_hidden -> decoder h0 ----------------
__global__ void enc_hidden_kernel(const float* __restrict__ enc_fc_w,
                                  const float* __restrict__ enc_fc_b) {
    int j = blockIdx.x, b = blockIdx.y;
    const float* hp = g_states_pre  + ((size_t)(S_ - 1) * B_ + b) * H_;
    const float* hq = g_states_post + ((size_t)(S_ - 1) * B_ + b) * H_;
    const float* wrow = enc_fc_w + (size_t)j * (2 * H_);
    float acc = 0.f;
    for (int k = threadIdx.x; k < H_; k += 128)
        acc += hp[k] * wrow[k] + hq[k] * wrow[H_ + k];
    acc = blockReduce128(acc);
    if (threadIdx.x == 0) g_dec_h0[b * H_ + j] = tanhf(acc + enc_fc_b[j]);
}

// ---------------- 6. score_enc ----------------
__global__ void score_enc_kernel(const float* __restrict__ out_w) {
    int c = blockIdx.x, b = blockIdx.y;
    int e = c >> 9, t = c & (S_ - 1);
    const float* src = (e ? g_states_post : g_states_pre) + ((size_t)t * B_ + b) * H_;
    float acc = 0.f;
    for (int h = threadIdx.x; h < H_; h += 128)
        acc += fmaxf(src[h], 0.f) * out_w[h];
    acc = blockReduce128(acc);
    if (threadIdx.x == 0) g_score[b * (2 * S_) + c] = acc;
}

// ---------------- 7. hscore ----------------
__global__ void hscore_kernel(const float* __restrict__ out_w, const float* __restrict__ out_b) {
    int t = blockIdx.x, b = blockIdx.y;
    const float* src = g_dstates + ((size_t)t * B_ + b) * H_;
    float acc = 0.f;
    for (int h = threadIdx.x; h < H_; h += 128)
        acc += fmaxf(src[h], 0.f) * out_w[H_ + h];
    acc = blockReduce128(acc);
    if (threadIdx.x == 0) g_hscore[b * T_ + t] = acc + out_b[0];
}

// ---------------- 8. final output: sigmoid fill ----------------
__global__ void output_kernel(float* __restrict__ out) {
    int idx = blockIdx.x * blockDim.x + threadIdx.x;
    int p  = idx >> 21;
    int r  = idx & ((1 << 21) - 1);
    int b  = r >> 15;
    int r2 = r & 32767;
    int t  = r2 >> 9;
    int s  = r2 & 511;
    float logit = g_score[b * (2 * S_) + p * S_ + s] + g_hscore[b * T_ + t];
    out[idx] = fast_sigmoid(logit);
}

// ---------------- host ----------------
extern "C" void kernel_launch(void* const* d_in, const int* in_sizes, int n_in,
                              void* d_out, int out_size) {
    const int*   pre_seq   = (const int*)  d_in[0];
    const int*   post_seq  = (const int*)  d_in[1];
    const int*   trg       = (const int*)  d_in[2];
    const float* emb       = (const float*)d_in[3];
    const float* pre_Wih   = (const float*)d_in[4];
    const float* pre_Whh   = (const float*)d_in[5];
    const float* pre_bih   = (const float*)d_in[6];
    const float* pre_bhh   = (const float*)d_in[7];
    const float* post_Wih  = (const float*)d_in[8];
    const float* post_Whh  = (const float*)d_in[9];
    const float* post_bih  = (const float*)d_in[10];
    const float* post_bhh  = (const float*)d_in[11];
    const float* enc_fc_w  = (const float*)d_in[12];
    const float* enc_fc_b  = (const float*)d_in[13];
    const float* dec_Wih   = (const float*)d_in[14];
    const float* dec_Whh   = (const float*)d_in[15];
    const float* dec_bih   = (const float*)d_in[16];
    const float* dec_bhh   = (const float*)d_in[17];
    const float* out_w     = (const float*)d_in[18];
    const float* out_b     = (const float*)d_in[19];
    float* out = (float*)d_out;

    float *gi_pre, *gi_post, *gi_dec, *wt_pre, *wt_post, *wt_dec;
    float *st_pre, *st_post, *dst, *dec_h0;
    int* dec_tok;
    unsigned int *bar_enc, *bar_dec;
    cudaGetSymbolAddress((void**)&gi_pre,  g_gi_pre);
    cudaGetSymbolAddress((void**)&gi_post, g_gi_post);
    cudaGetSymbolAddress((void**)&gi_dec,  g_gi_dec);
    cudaGetSymbolAddress((void**)&wt_pre,  g_WT_pre);
    cudaGetSymbolAddress((void**)&wt_post, g_WT_post);
    cudaGetSymbolAddress((void**)&wt_dec,  g_WT_dec);
    cudaGetSymbolAddress((void**)&st_pre,  g_states_pre);
    cudaGetSymbolAddress((void**)&st_post, g_states_post);
    cudaGetSymbolAddress((void**)&dst,     g_dstates);
    cudaGetSymbolAddress((void**)&dec_h0,  g_dec_h0);
    cudaGetSymbolAddress((void**)&dec_tok, g_dec_tokens);
    cudaGetSymbolAddress((void**)&bar_enc, g_bar_enc);
    cudaGetSymbolAddress((void**)&bar_dec, g_bar_dec);

    cudaFuncSetAttribute(gru_persistent, cudaFuncAttributeMaxDynamicSharedMemorySize, PERS_SMEM);

    reset_bar_kernel<<<1, 32>>>();

    dim3 tb(32, 8);
    transpose_k<<<dim3(16, 48), tb>>>(pre_Wih,  wt_pre);
    transpose_k<<<dim3(16, 48), tb>>>(post_Wih, wt_post);
    transpose_k<<<dim3(16, 48), tb>>>(dec_Wih,  wt_dec);

    dec_tokens_kernel<<<16, 256>>>(pre_seq, trg);

    gi_gemm<<<dim3(12, 256), 256>>>(pre_seq,  emb, wt_pre,  pre_bih,  gi_pre);
    gi_gemm<<<dim3(12, 256), 256>>>(post_seq, emb, wt_post, post_bih, gi_post);
    gi_gemm<<<dim3(12, 32),  256>>>(dec_tok,  emb, wt_dec,  dec_bih,  gi_dec);

    // encoder recurrence: one persistent kernel, both GRUs (128 blocks)
    gru_persistent<<<128, PERS_THREADS, PERS_SMEM>>>(
        pre_Whh, pre_bhh, gi_pre, st_pre,
        post_Whh, post_bhh, gi_post, st_post,
        nullptr, S_, S_, 128, bar_enc);

    enc_hidden_kernel<<<dim3(H_, B_), 128>>>(enc_fc_w, enc_fc_b);
    score_enc_kernel<<<dim3(2 * S_, B_), 128>>>(out_w);

    // decoder recurrence: one persistent kernel (64 blocks, gru index always 0)
    gru_persistent<<<64, PERS_THREADS, PERS_SMEM>>>(
        dec_Whh, dec_bhh, gi_dec, dst,
        dec_Whh, dec_bhh, gi_dec, dst,
        dec_h0, T_, T_, 64, bar_dec);

    hscore_kernel<<<dim3(T_, B_), 128>>>(out_w, out_b);
    output_kernel<<<(2 * B_ * T_ * S_) / 256, 256>>>(out);
}

// round 10
// speedup vs baseline: 1.3017x; 1.1688x over previous
#include <cuda_runtime.h>
#include <cuda_bf16.h>
#include <cstdint>
#include <cstddef>

// Problem dims
#define B_  64
#define S_  512
#define T_  64
#define H_  512
#define D_  512
#define G_  1536   // 3*H

// ---------------- scratch (static device allocations) ----------------
__device__ float g_gi_pre [B_ * S_ * G_];
__device__ float g_gi_post[B_ * S_ * G_];
__device__ float g_gi_dec [B_ * T_ * G_];
__device__ float g_WT_pre [D_ * G_];
__device__ float g_WT_post[D_ * G_];
__device__ float g_WT_dec [D_ * G_];
__device__ float g_states_pre [S_ * B_ * H_];
__device__ float g_states_post[S_ * B_ * H_];
__device__ float g_dstates    [T_ * B_ * H_];
__device__ float g_dec_h0 [B_ * H_];
__device__ float g_score  [B_ * 2 * S_];
__device__ float g_hscore [B_ * T_];
__device__ int   g_dec_tokens[B_ * T_];
__device__ unsigned int g_bar_enc;
__device__ unsigned int g_bar_dec;

// ---------------- helpers ----------------
__device__ __forceinline__ float fast_sigmoid(float x) {
    return 1.0f / (1.0f + __expf(-x));
}

__device__ __forceinline__ float blockReduce128(float v) {
    __shared__ float red[4];
    #pragma unroll
    for (int o = 16; o; o >>= 1) v += __shfl_xor_sync(0xffffffffu, v, o);
    if ((threadIdx.x & 31) == 0) red[threadIdx.x >> 5] = v;
    __syncthreads();
    if (threadIdx.x == 0) v = red[0] + red[1] + red[2] + red[3];
    return v;
}

__device__ __forceinline__ float pk_lo(unsigned long long p) {
    return __uint_as_float((unsigned)(p & 0xffffffffull));
}
__device__ __forceinline__ float pk_hi(unsigned long long p) {
    return __uint_as_float((unsigned)(p >> 32));
}

// L2-only (bypass L1) vector load/store for cross-block h exchange
__device__ __forceinline__ float4 ldg_cg_v4(const float* p) {
    float4 v;
    asm volatile("ld.global.cg.v4.f32 {%0,%1,%2,%3},[%4];"
                 : "=f"(v.x), "=f"(v.y), "=f"(v.z), "=f"(v.w) : "l"(p));
    return v;
}
__device__ __forceinline__ void stg_cg_f32(float* p, float v) {
    asm volatile("st.global.cg.f32 [%0],%1;" :: "l"(p), "f"(v) : "memory");
}

// ---------------- 0. barrier reset ----------------
__global__ void reset_bar_kernel() {
    if (threadIdx.x == 0) { g_bar_enc = 0u; g_bar_dec = 0u; }
}

// ---------------- 1. transpose Wih (1536 x 512) -> WT (512 x 1536) ----------------
__global__ void transpose_k(const float* __restrict__ src, float* __restrict__ dst) {
    __shared__ float tile[32][33];
    int x = blockIdx.x * 32 + threadIdx.x;
    int y = blockIdx.y * 32 + threadIdx.y;
    #pragma unroll
    for (int i = 0; i < 32; i += 8)
        tile[threadIdx.y + i][threadIdx.x] = src[(size_t)(y + i) * D_ + x];
    __syncthreads();
    int x2 = blockIdx.y * 32 + threadIdx.x;
    int y2 = blockIdx.x * 32 + threadIdx.y;
    #pragma unroll
    for (int i = 0; i < 32; i += 8)
        dst[(size_t)(y2 + i) * G_ + x2] = tile[threadIdx.x][threadIdx.y + i];
}

// ---------------- 2. build decoder tokens ----------------
__global__ void dec_tokens_kernel(const int* __restrict__ pre_seq, const int* __restrict__ trg) {
    int idx = blockIdx.x * blockDim.x + threadIdx.x;
    if (idx >= B_ * T_) return;
    int b = idx >> 6;
    int t = idx & 63;
    g_dec_tokens[idx] = (t == 0) ? pre_seq[b * S_ + (S_ - 1)] : trg[b * T_ + t - 1];
}

// ---------------- 3. gi GEMM (128x128x8 tiles, 256 thr, 8x8/thread, f32x2) ----------------
__global__ __launch_bounds__(256, 2)
void gi_gemm(const int* __restrict__ tokens,
             const float* __restrict__ emb,
             const float* __restrict__ WT,
             const float* __restrict__ bias,
             float* __restrict__ out) {
    __shared__ float As[8][128];
    __shared__ float Bs[8][128];
    int tid  = threadIdx.x;
    int row0 = blockIdx.y * 128;
    int col0 = blockIdx.x * 128;

    int ar = tid >> 1;
    int ac = (tid & 1) * 4;
    int token = tokens[row0 + ar];
    const float* arow = emb + (size_t)token * D_ + ac;

    int br = tid >> 5;
    int bc = (tid & 31) * 4;
    const float* bptr = WT + (size_t)br * G_ + col0 + bc;

    int tr = (tid >> 4) * 8;
    int tc = (tid & 15) * 8;

    // packed accumulators: acc2[i][jp] covers cols (2*jp, 2*jp+1)
    unsigned long long acc2[8][4];
    #pragma unroll
    for (int i = 0; i < 8; i++)
        #pragma unroll
        for (int j = 0; j < 4; j++) acc2[i][j] = 0ull;

    for (int k0 = 0; k0 < D_; k0 += 8) {
        float4 av = *(const float4*)(arow + k0);
        As[ac + 0][ar] = av.x; As[ac + 1][ar] = av.y;
        As[ac + 2][ar] = av.z; As[ac + 3][ar] = av.w;
        float4 bv = *(const float4*)(bptr + (size_t)k0 * G_);
        *(float4*)&Bs[br][bc] = bv;
        __syncthreads();
        #pragma unroll
        for (int k = 0; k < 8; k++) {
            float a[8];
            *(float4*)(a)      = *(const float4*)&As[k][tr];
            *(float4*)(a + 4)  = *(const float4*)&As[k][tr + 4];
            ulonglong2 bl = *(const ulonglong2*)&Bs[k][tc];
            ulonglong2 bh = *(const ulonglong2*)&Bs[k][tc + 4];
            #pragma unroll
            for (int i = 0; i < 8; i++) {
                unsigned long long a2;
                asm("mov.b64 %0,{%1,%1};" : "=l"(a2) : "f"(a[i]));
                asm("fma.rn.f32x2 %0,%1,%2,%0;" : "+l"(acc2[i][0]) : "l"(a2), "l"(bl.x));
                asm("fma.rn.f32x2 %0,%1,%2,%0;" : "+l"(acc2[i][1]) : "l"(a2), "l"(bl.y));
                asm("fma.rn.f32x2 %0,%1,%2,%0;" : "+l"(acc2[i][2]) : "l"(a2), "l"(bh.x));
                asm("fma.rn.f32x2 %0,%1,%2,%0;" : "+l"(acc2[i][3]) : "l"(a2), "l"(bh.y));
            }
        }
        __syncthreads();
    }

    #pragma unroll
    for (int i = 0; i < 8; i++) {
        #pragma unroll
        for (int j = 0; j < 8; j += 4) {
            float4 v;
            v.x = pk_lo(acc2[i][j / 2])     + bias[col0 + tc + j + 0];
            v.y = pk_hi(acc2[i][j / 2])     + bias[col0 + tc + j + 1];
            v.z = pk_lo(acc2[i][j / 2 + 1]) + bias[col0 + tc + j + 2];
            v.w = pk_hi(acc2[i][j / 2 + 1]) + bias[col0 + tc + j + 3];
            *(float4*)&out[(size_t)(row0 + tr + i) * G_ + col0 + tc + j] = v;
        }
    }
}

// ---------------- 4. persistent GRU recurrence (register-resident W) ----------------
// Grid: 64 blocks per GRU (4 batch-quarters x 16 j-chunks of 32), 384 threads.
// Warp w: g = w>>2 (gate), q = w&3 (k-quarter); lane = jl.
// Per step: prefetch gi -> stage h -> K loop (reg W x smem h) -> exchange partials
// -> gate phase -> release-arrive / acquire-wait grid barrier (no membars).
#define PERS_THREADS 384
#define PERS_SMEM ((16 * 512 + 4 * 3 * 16 * 32) * 4)   // 57,344 B

__global__ __launch_bounds__(PERS_THREADS, 1)
void gru_persistent(const float* __restrict__ Whh0, const float* __restrict__ bhh0,
                    const float* __restrict__ gi0,  float* __restrict__ st0,
                    const float* __restrict__ Whh1, const float* __restrict__ bhh1,
                    const float* __restrict__ gi1,  float* __restrict__ st1,
                    const float* __restrict__ hinit,   // nullptr => zeros
                    int nsteps, int gi_sstride, int nblk, unsigned int* bar) {
    extern __shared__ float sm[];
    float* hs   = sm;                  // [16][512]
    float* part = sm + 16 * 512;       // [4 q][3 g][16 b][32 jl]

    int tid  = threadIdx.x;
    int lane = tid & 31;               // jl
    int w    = tid >> 5;
    int q    = w & 3;                  // k-quarter
    int g    = w >> 2;                 // gate 0..2

    int bid  = blockIdx.x;
    int gru  = bid >> 6;
    int r    = bid & 63;
    int b0   = (r >> 4) * 16;
    int j0   = (r & 15) * 32;

    const float* Whh = gru ? Whh1 : Whh0;
    const float* bhh = gru ? bhh1 : bhh0;
    const float* gi  = gru ? gi1  : gi0;
    float*       st  = gru ? st1  : st0;

    // ---- load W slice into registers once: 128 floats = 64 f32x2 ----
    unsigned long long wreg[64];
    {
        const unsigned long long* wp = (const unsigned long long*)
            (Whh + ((size_t)(g * H_ + j0 + lane)) * H_ + q * 128);
        #pragma unroll
        for (int i = 0; i < 64; i++) wreg[i] = wp[i];
    }

    uint32_t smem_base = (uint32_t)__cvta_generic_to_shared(sm);
    uint32_t hq_base   = smem_base + (uint32_t)(q * 128) * 4u;
    uint32_t part_base = smem_base + 16u * 512u * 4u;
    uint32_t part_my   = part_base + (uint32_t)(((q * 3 + g) * 16) * 32 + lane) * 4u;

    // gate-phase output assignments (step-invariant)
    int o0 = tid;            // < 512 always
    int o1 = tid + 384;      // valid if < 512
    int ob0 = o0 >> 5, ojl0 = o0 & 31;
    int ob1 = o1 >> 5, ojl1 = o1 & 31;
    int jg0 = j0 + ojl0, bg0 = b0 + ob0;
    int jg1 = j0 + ojl1, bg1 = b0 + ob1;
    bool has1 = (o1 < 512);

    // biases: hoisted out of the time loop
    float br0 = __ldg(bhh + jg0), bz0 = __ldg(bhh + H_ + jg0), bn0 = __ldg(bhh + 2 * H_ + jg0);
    float br1 = 0.f, bz1 = 0.f, bn1 = 0.f;
    if (has1) { br1 = __ldg(bhh + jg1); bz1 = __ldg(bhh + H_ + jg1); bn1 = __ldg(bhh + 2 * H_ + jg1); }

    const float* gibase0 = gi + (size_t)bg0 * gi_sstride * G_;
    const float* gibase1 = gi + (size_t)bg1 * gi_sstride * G_;

    for (int t = 0; t < nsteps; t++) {
        // ---- prefetch gi for this step (DRAM latency hides under staging + K) ----
        const float* gp0 = gibase0 + (size_t)t * G_;
        float gir0 = __ldg(gp0 + jg0);
        float giz0 = __ldg(gp0 + H_ + jg0);
        float gin0 = __ldg(gp0 + 2 * H_ + jg0);
        float gir1 = 0.f, giz1 = 0.f, gin1 = 0.f;
        if (has1) {
            const float* gp1 = gibase1 + (size_t)t * G_;
            gir1 = __ldg(gp1 + jg1);
            giz1 = __ldg(gp1 + H_ + jg1);
            gin1 = __ldg(gp1 + 2 * H_ + jg1);
        }

        // ---- stage h_prev (16 rows x 512) via L2 (.cg) ----
        const float* hp = (t == 0) ? hinit : (st + (size_t)(t - 1) * B_ * H_);
        if (hp) {
            const float* src = hp + (size_t)b0 * H_;
            for (int i = tid; i < 2048; i += PERS_THREADS) {
                float4 v = ldg_cg_v4(src + i * 4);
                *(float4*)&hs[i * 4] = v;
            }
        } else {
            float4 z = make_float4(0.f, 0.f, 0.f, 0.f);
            float4* dst = (float4*)hs;
            for (int i = tid; i < 2048; i += PERS_THREADS) dst[i] = z;
        }
        __syncthreads();

        // ---- K loop: partial[b] = sum_{k in quarter} W[n][k] * h[b][k] ----
        for (int b = 0; b < 16; b++) {
            uint32_t ha = hq_base + (uint32_t)b * (512u * 4u);
            unsigned long long a0 = 0ull, a1 = 0ull;
            #pragma unroll
            for (int i = 0; i < 32; i++) {
                unsigned long long h0, h1;
                asm("ld.shared.v2.u64 {%0,%1},[%2];"
                    : "=l"(h0), "=l"(h1) : "r"(ha + (uint32_t)(i * 16)));
                asm("fma.rn.f32x2 %0,%1,%2,%0;" : "+l"(a0) : "l"(wreg[2 * i]),     "l"(h0));
                asm("fma.rn.f32x2 %0,%1,%2,%0;" : "+l"(a1) : "l"(wreg[2 * i + 1]), "l"(h1));
            }
            float s = pk_lo(a0) + pk_hi(a0) + pk_lo(a1) + pk_hi(a1);
            asm volatile("st.shared.f32 [%0],%1;"
                         :: "r"(part_my + (uint32_t)b * (32u * 4u)), "f"(s));
        }
        __syncthreads();

        // ---- gate phase: 512 outputs (16 b x 32 jl) ----
        float* h_out = st + (size_t)t * B_ * H_;
        {
            int b = ob0, jl = ojl0;
            float hr = 0.f, hz = 0.f, hn = 0.f;
            #pragma unroll
            for (int qq = 0; qq < 4; qq++) {
                hr += part[((qq * 3 + 0) * 16 + b) * 32 + jl];
                hz += part[((qq * 3 + 1) * 16 + b) * 32 + jl];
                hn += part[((qq * 3 + 2) * 16 + b) * 32 + jl];
            }
            float rr = fast_sigmoid(gir0 + hr + br0);
            float zz = fast_sigmoid(giz0 + hz + bz0);
            float nn = tanhf(gin0 + rr * (hn + bn0) + 0.f * bn0 - 0.f);
            // NOTE: reference is n = tanh(inn + r*(hn_dot + bnn)) with bnn inside r*():
            // gh = h@Whh.T + bhh  => hn includes bhh_n; so compute properly below.
            nn = tanhf(gin0 + rr * (hn + bn0));
            float hprev = hs[b * H_ + jg0 - j0 + j0];   // hs[b*H_ + jg0]
            hprev = hs[b * H_ + jg0];
            stg_cg_f32(h_out + (size_t)bg0 * H_ + jg0, (1.0f - zz) * nn + zz * hprev);
        }
        if (has1) {
            int b = ob1, jl = ojl1;
            float hr = 0.f, hz = 0.f, hn = 0.f;
            #pragma unroll
            for (int qq = 0; qq < 4; qq++) {
                hr += part[((qq * 3 + 0) * 16 + b) * 32 + jl];
                hz += part[((qq * 3 + 1) * 16 + b) * 32 + jl];
                hn += part[((qq * 3 + 2) * 16 + b) * 32 + jl];
            }
            float rr = fast_sigmoid(gir1 + hr + br1);
            float zz = fast_sigmoid(giz1 + hz + bz1);
            float nn = tanhf(gin1 + rr * (hn + bn1));
            float hprev = hs[b * H_ + jg1];
            stg_cg_f32(h_out + (size_t)bg1 * H_ + jg1, (1.0f - zz) * nn + zz * hprev);
        }

        // ---- grid barrier: release arrive, acquire wait (no extra membars) ----
        __syncthreads();
        if (tid == 0) {
            asm volatile("red.release.gpu.global.add.u32 [%0],1;" :: "l"(bar) : "memory");
            unsigned int target = (unsigned int)(t + 1) * (unsigned int)nblk;
            unsigned int v;
            do {
                asm volatile("ld.acquire.gpu.global.u32 %0,[%1];" : "=r"(v) : "l"(bar) : "memory");
            } while (v < target);
        }
        __syncthreads();
    }
}

// ---------------- 5. enc_hidden -> decoder h0 ----------------
__global__ void enc_hidden_kernel(const float* __restrict__ enc_fc_w,
                                  const float* __restrict__ enc_fc_b) {
    int j = blockIdx.x, b = blockIdx.y;
    const float* hp = g_states_pre  + ((size_t)(S_ - 1) * B_ + b) * H_;
    const float* hq = g_states_post + ((size_t)(S_ - 1) * B_ + b) * H_;
    const float* wrow = enc_fc_w + (size_t)j * (2 * H_);
    float acc = 0.f;
    for (int k = threadIdx.x; k < H_; k += 128)
        acc += hp[k] * wrow[k] + hq[k] * wrow[H_ + k];
    acc = blockReduce128(acc);
    if (threadIdx.x == 0) g_dec_h0[b * H_ + j] = tanhf(acc + enc_fc_b[j]);
}

// ---------------- 6. score_enc ----------------
__global__ void score_enc_kernel(const float* __restrict__ out_w) {
    int c = blockIdx.x, b = blockIdx.y;
    int e = c >> 9, t = c & (S_ - 1);
    const float* src = (e ? g_states_post : g_states_pre) + ((size_t)t * B_ + b) * H_;
    float acc = 0.f;
    for (int h = threadIdx.x; h < H_; h += 128)
        acc += fmaxf(src[h], 0.f) * out_w[h];
    acc = blockReduce128(acc);
    if (threadIdx.x == 0) g_score[b * (2 * S_) + c] = acc;
}

// ---------------- 7. hscore ----------------
__global__ void hscore_kernel(const float* __restrict__ out_w, const float* __restrict__ out_b) {
    int t = blockIdx.x, b = blockIdx.y;
    const float* src = g_dstates + ((size_t)t * B_ + b) * H_;
    float acc = 0.f;
    for (int h = threadIdx.x; h < H_; h += 128)
        acc += fmaxf(src[h], 0.f) * out_w[H_ + h];
    acc = blockReduce128(acc);
    if (threadIdx.x == 0) g_hscore[b * T_ + t] = acc + out_b[0];
}

// ---------------- 8. final output: sigmoid fill ----------------
__global__ void output_kernel(float* __restrict__ out) {
    int idx = blockIdx.x * blockDim.x + threadIdx.x;
    int p  = idx >> 21;
    int r  = idx & ((1 << 21) - 1);
    int b  = r >> 15;
    int r2 = r & 32767;
    int t  = r2 >> 9;
    int s  = r2 & 511;
    float logit = g_score[b * (2 * S_) + p * S_ + s] + g_hscore[b * T_ + t];
    out[idx] = fast_sigmoid(logit);
}

// ---------------- host ----------------
extern "C" void kernel_launch(void* const* d_in, const int* in_sizes, int n_in,
                              void* d_out, int out_size) {
    const int*   pre_seq   = (const int*)  d_in[0];
    const int*   post_seq  = (const int*)  d_in[1];
    const int*   trg       = (const int*)  d_in[2];
    const float* emb       = (const float*)d_in[3];
    const float* pre_Wih   = (const float*)d_in[4];
    const float* pre_Whh   = (const float*)d_in[5];
    const float* pre_bih   = (const float*)d_in[6];
    const float* pre_bhh   = (const float*)d_in[7];
    const float* post_Wih  = (const float*)d_in[8];
    const float* post_Whh  = (const float*)d_in[9];
    const float* post_bih  = (const float*)d_in[10];
    const float* post_bhh  = (const float*)d_in[11];
    const float* enc_fc_w  = (const float*)d_in[12];
    const float* enc_fc_b  = (const float*)d_in[13];
    const float* dec_Wih   = (const float*)d_in[14];
    const float* dec_Whh   = (const float*)d_in[15];
    const float* dec_bih   = (const float*)d_in[16];
    const float* dec_bhh   = (const float*)d_in[17];
    const float* out_w     = (const float*)d_in[18];
    const float* out_b     = (const float*)d_in[19];
    float* out = (float*)d_out;

    float *gi_pre, *gi_post, *gi_dec, *wt_pre, *wt_post, *wt_dec;
    float *st_pre, *st_post, *dst, *dec_h0;
    int* dec_tok;
    unsigned int *bar_enc, *bar_dec;
    cudaGetSymbolAddress((void**)&gi_pre,  g_gi_pre);
    cudaGetSymbolAddress((void**)&gi_post, g_gi_post);
    cudaGetSymbolAddress((void**)&gi_dec,  g_gi_dec);
    cudaGetSymbolAddress((void**)&wt_pre,  g_WT_pre);
    cudaGetSymbolAddress((void**)&wt_post, g_WT_post);
    cudaGetSymbolAddress((void**)&wt_dec,  g_WT_dec);
    cudaGetSymbolAddress((void**)&st_pre,  g_states_pre);
    cudaGetSymbolAddress((void**)&st_post, g_states_post);
    cudaGetSymbolAddress((void**)&dst,     g_dstates);
    cudaGetSymbolAddress((void**)&dec_h0,  g_dec_h0);
    cudaGetSymbolAddress((void**)&dec_tok, g_dec_tokens);
    cudaGetSymbolAddress((void**)&bar_enc, g_bar_enc);
    cudaGetSymbolAddress((void**)&bar_dec, g_bar_dec);

    cudaFuncSetAttribute(gru_persistent, cudaFuncAttributeMaxDynamicSharedMemorySize, PERS_SMEM);

    reset_bar_kernel<<<1, 32>>>();

    dim3 tb(32, 8);
    transpose_k<<<dim3(16, 48), tb>>>(pre_Wih,  wt_pre);
    transpose_k<<<dim3(16, 48), tb>>>(post_Wih, wt_post);
    transpose_k<<<dim3(16, 48), tb>>>(dec_Wih,  wt_dec);

    dec_tokens_kernel<<<16, 256>>>(pre_seq, trg);

    gi_gemm<<<dim3(12, 256), 256>>>(pre_seq,  emb, wt_pre,  pre_bih,  gi_pre);
    gi_gemm<<<dim3(12, 256), 256>>>(post_seq, emb, wt_post, post_bih, gi_post);
    gi_gemm<<<dim3(12, 32),  256>>>(dec_tok,  emb, wt_dec,  dec_bih,  gi_dec);

    // encoder recurrence: one persistent kernel, both GRUs (128 blocks)
    gru_persistent<<<128, PERS_THREADS, PERS_SMEM>>>(
        pre_Whh, pre_bhh, gi_pre, st_pre,
        post_Whh, post_bhh, gi_post, st_post,
        nullptr, S_, S_, 128, bar_enc);

    enc_hidden_kernel<<<dim3(H_, B_), 128>>>(enc_fc_w, enc_fc_b);
    score_enc_kernel<<<dim3(2 * S_, B_), 128>>>(out_w);

    // decoder recurrence: one persistent kernel (64 blocks)
    gru_persistent<<<64, PERS_THREADS, PERS_SMEM>>>(
        dec_Whh, dec_bhh, gi_dec, dst,
        dec_Whh, dec_bhh, gi_dec, dst,
        dec_h0, T_, T_, 64, bar_dec);

    hscore_kernel<<<dim3(T_, B_), 128>>>(out_w, out_b);
    output_kernel<<<(2 * B_ * T_ * S_) / 256, 256>>>(out);
}